// round 7
// baseline (speedup 1.0000x reference)
#include <cuda_runtime.h>

#define NN 1024
#define BB 128

// energy[b] = 0.5 * sum_{i<=j} W_ij * (1 + u_bi * u_bj),  u = 2v - 1.
// Grid (16,16,2): 64x64 W tiles (upper triangle only) x 2 batch-groups of 64.
// Each block: Q_i(b) = sum_{j in tile} Wmasked_ij * u_bj (register GEMM),
// then atomicAdd 0.5*(sum_i u_bi Q_i(b) + T0_partial) into out[b].
__global__ __launch_bounds__(256) void potts_kernel(const float* __restrict__ V,
                                                    const float* __restrict__ W,
                                                    float* __restrict__ out) {
    __shared__ float Ws[64][64];   // masked W tile [i][j]; float4 reads are warp-uniform broadcast
    __shared__ float Uj[64][64];   // u tile, j-range: Uj[j][b ^ (j&31)] (XOR swizzle, conflict-free)
    __shared__ float Ui[64][64];   // u tile, i-range: Ui[i][b ^ (i&31)]

    int ti = blockIdx.x, tj = blockIdx.y, bz = blockIdx.z;
    if (tj < ti) return;
    int i0 = ti * 64, j0 = tj * 64, b0 = bz * 64;
    int tid = threadIdx.x;
    bool diag = (ti == tj);

    // ---- Load W tile (coalesced float4), mask j<i on diagonal tiles ----
    {
        int r  = tid >> 4;          // 0..15
        int c4 = (tid & 15) << 2;   // 0,4,...,60
        #pragma unroll
        for (int rep = 0; rep < 4; rep++) {
            int row = r + rep * 16;
            float4 w = *(const float4*)&W[(size_t)(i0 + row) * NN + j0 + c4];
            if (diag) {
                if (c4 + 0 < row) w.x = 0.0f;
                if (c4 + 1 < row) w.y = 0.0f;
                if (c4 + 2 < row) w.z = 0.0f;
                if (c4 + 3 < row) w.w = 0.0f;
            }
            *(float4*)&Ws[row][c4] = w;
        }
    }
    // ---- Load u tiles (coalesced gmem; swizzled conflict-free smem writes) ----
    {
        int j  = tid & 63;          // lane-consecutive -> coalesced gmem, distinct banks
        int bq = tid >> 6;          // 0..3
        #pragma unroll
        for (int rep = 0; rep < 16; rep++) {
            int b = bq + rep * 4;
            float vj = V[(size_t)(b0 + b) * NN + j0 + j];
            Uj[j][b ^ (j & 31)] = fmaf(2.0f, vj, -1.0f);
            float vi = V[(size_t)(b0 + b) * NN + i0 + j];   // same j used as i-index
            Ui[j][b ^ (j & 31)] = fmaf(2.0f, vi, -1.0f);
        }
    }
    __syncthreads();

    int bb = tid & 63;   // batch lane: consecutive within warp -> conflict-free swizzled reads
    int ig = tid >> 6;   // i-group 0..3: warp-uniform -> broadcast Ws float4 reads

    float acc[16];
    #pragma unroll
    for (int ii = 0; ii < 16; ii++) acc[ii] = 0.0f;

    #pragma unroll 4
    for (int j4 = 0; j4 < 64; j4 += 4) {
        float u0 = Uj[j4 + 0][bb ^ ((j4 + 0) & 31)];
        float u1 = Uj[j4 + 1][bb ^ ((j4 + 1) & 31)];
        float u2 = Uj[j4 + 2][bb ^ ((j4 + 2) & 31)];
        float u3 = Uj[j4 + 3][bb ^ ((j4 + 3) & 31)];
        #pragma unroll
        for (int ii = 0; ii < 16; ii++) {
            float4 w = *(const float4*)&Ws[ig * 16 + ii][j4];
            float a = acc[ii];
            a = fmaf(w.x, u0, a);
            a = fmaf(w.y, u1, a);
            a = fmaf(w.z, u2, a);
            a = fmaf(w.w, u3, a);
            acc[ii] = a;
        }
    }

    // ---- Tile row sums r_i -> Ws[i][0] (Ws is dead after the GEMM) ----
    __syncthreads();
    if (tid < 64) {
        float rs = 0.0f;
        #pragma unroll 8
        for (int j = 0; j < 64; j++) {
            int jj = (j + tid) & 63;   // rotate -> conflict-free
            rs += Ws[tid][jj];
        }
        Ws[tid][0] = rs;               // row i touched only by thread i
    }
    __syncthreads();

    // ---- Epilogue: out[b] += 0.5 * (sum_i u_bi Q_i(b) + sum_i r_i) ----
    float e = 0.0f, t0 = 0.0f;
    #pragma unroll
    for (int ii = 0; ii < 16; ii++) {
        int row = ig * 16 + ii;
        e  = fmaf(acc[ii], Ui[row][bb ^ (row & 31)], e);
        t0 += Ws[row][0];              // broadcast read
    }
    atomicAdd(&out[b0 + bb], 0.5f * (e + t0));
}

extern "C" void kernel_launch(void* const* d_in, const int* in_sizes, int n_in,
                              void* d_out, int out_size) {
    // Defensive input identification by element count (vector: 128*1024,
    // interactions: 1024*1024) — robust to metadata ordering.
    const float* V = (const float*)d_in[0];
    const float* W = (const float*)d_in[1];
    if (n_in >= 2 && in_sizes[0] == NN * NN && in_sizes[1] == BB * NN) {
        V = (const float*)d_in[1];
        W = (const float*)d_in[0];
    }
    float* out = (float*)d_out;               // [128] fp32

    cudaMemsetAsync(out, 0, sizeof(float) * BB);   // out is poisoned; we accumulate into it
    dim3 grid(16, 16, 2);
    potts_kernel<<<grid, 256>>>(V, W, out);
}